// round 6
// baseline (speedup 1.0000x reference)
#include <cuda_runtime.h>
#include <math.h>

#define NEG_INF_VAL -10000000000.0f

namespace {
constexpr int Hc = 512;
constexpr int Sc = 1024;
constexpr int KS = 8;          // split-K partials for H=512 GEMMs
constexpr int SLICES = 16;     // attn slices per beam
constexpr int NPART = 64 * SLICES;  // 1024

// float scratch offsets
constexpr int OFF_GIP     = 0;                          // KS*64*1536
constexpr int OFF_GHP     = OFF_GIP + KS * 64 * 1536;
constexpr int OFF_QP      = OFF_GHP + KS * 64 * 1536;   // KS*64*512
constexpr int OFF_HNEW    = OFF_QP + KS * 64 * 512;
constexpr int OFF_QB1     = OFF_HNEW + 64 * 512;
constexpr int OFF_ATTN    = OFF_QB1 + 64;               // 64x1024
constexpr int OFF_PARTM   = OFF_ATTN + 64 * 1024;
constexpr int OFF_PARTL   = OFF_PARTM + NPART;
constexpr int OFF_PARTACC = OFF_PARTL + NPART;          // 1024*512
constexpr int OFF_CTXRAW  = OFF_PARTACC + NPART * 512;
constexpr int OFF_RESULT  = OFF_CTXRAW + 64 * 512;
constexpr int OFF_TKLOG   = OFF_RESULT + 64 * 512;      // 256
constexpr int OFF_W32     = OFF_TKLOG + 256;            // 512*512
constexpr int OFF_BVEC    = OFF_W32 + 512 * 512;        // 512
constexpr int SCR_TOTAL   = OFF_BVEC + 512;

// output layout (floats), tuple members concatenated in order
constexpr int O_RESULT = 0;
constexpr int O_HIDDEN = 32768;
constexpr int O_IDX    = 65536;
constexpr int O_ATTNS  = 65792;
constexpr int O_MASK   = 327936;
constexpr int O_SCORES = 393472;
}

__device__ __align__(16) float g_scr[SCR_TOTAL];
__device__ int g_tkidx[256];

// ---------------- GEMM tiles (64 rows x 64 cols, K-chunk = ITERS*32) ----------------
template<int ITERS, bool ATOMIC>
__device__ __forceinline__ void gemm_bt_tile(const float* __restrict__ A, int lda,
                                             const float* __restrict__ B, int ldb,
                                             float* __restrict__ C, int ldc,
                                             const float* __restrict__ bias, bool addBias,
                                             int j0, int k0,
                                             float (*As)[65], float (*Bs)[65]) {
    const int t = threadIdx.x;
    const int bx = (t & 15) * 4;
    const int by = (t >> 4) * 4;
    float acc[4][4] = {};
#pragma unroll
    for (int it = 0; it < ITERS; it++) {
        const int kk = k0 + it * 32;
#pragma unroll
        for (int i = 0; i < 8; i++) {
            int idx = t + i * 256;
            int r = idx >> 5, c = idx & 31;
            As[c][r] = A[r * lda + kk + c];
            Bs[c][r] = B[(j0 + r) * ldb + kk + c];
        }
        __syncthreads();
#pragma unroll
        for (int c = 0; c < 32; c++) {
            float b0 = Bs[c][bx + 0], b1 = Bs[c][bx + 1], b2 = Bs[c][bx + 2], b3 = Bs[c][bx + 3];
#pragma unroll
            for (int r = 0; r < 4; r++) {
                float av = As[c][by + r];
                acc[r][0] += av * b0; acc[r][1] += av * b1;
                acc[r][2] += av * b2; acc[r][3] += av * b3;
            }
        }
        __syncthreads();
    }
#pragma unroll
    for (int r = 0; r < 4; r++)
#pragma unroll
        for (int cc = 0; cc < 4; cc++) {
            float v = acc[r][cc];
            if (addBias) v += bias[j0 + bx + cc];
            if (ATOMIC) atomicAdd(&C[(by + r) * ldc + j0 + bx + cc], v);
            else        C[(by + r) * ldc + j0 + bx + cc] = v;
        }
}

template<int ITERS>
__device__ __forceinline__ void gemm_ab_tile(const float* __restrict__ A, int lda,
                                             const float* __restrict__ B, int ldb,
                                             float* __restrict__ C, int ldc,
                                             int j0, int k0,
                                             float (*As)[65], float (*Bs)[65]) {
    const int t = threadIdx.x;
    const int bx = (t & 15) * 4;
    const int by = (t >> 4) * 4;
    float acc[4][4] = {};
#pragma unroll
    for (int it = 0; it < ITERS; it++) {
        const int kk = k0 + it * 32;
#pragma unroll
        for (int i = 0; i < 8; i++) {
            int idx = t + i * 256;
            int r = idx >> 5, c = idx & 31;
            As[c][r] = A[r * lda + kk + c];
        }
#pragma unroll
        for (int i = 0; i < 8; i++) {
            int idx = t + i * 256;
            int c = idx >> 6, jj = idx & 63;
            Bs[c][jj] = B[(kk + c) * ldb + j0 + jj];
        }
        __syncthreads();
#pragma unroll
        for (int c = 0; c < 32; c++) {
            float b0 = Bs[c][bx + 0], b1 = Bs[c][bx + 1], b2 = Bs[c][bx + 2], b3 = Bs[c][bx + 3];
#pragma unroll
            for (int r = 0; r < 4; r++) {
                float av = As[c][by + r];
                acc[r][0] += av * b0; acc[r][1] += av * b1;
                acc[r][2] += av * b2; acc[r][3] += av * b3;
            }
        }
        __syncthreads();
    }
#pragma unroll
    for (int r = 0; r < 4; r++)
#pragma unroll
        for (int cc = 0; cc < 4; cc++)
            C[(by + r) * ldc + j0 + bx + cc] = acc[r][cc];
}

// ---- gi/gh partials: grid (24, KS, 2), block 256 ----
__global__ void __launch_bounds__(256) k_gru(const float* __restrict__ x, const float* __restrict__ h,
                                             const float* __restrict__ wih, const float* __restrict__ whh) {
    __shared__ float As[32][65];
    __shared__ float Bs[32][65];
    const float* A = blockIdx.z ? h : x;
    const float* B = blockIdx.z ? whh : wih;
    float* C = g_scr + (blockIdx.z ? OFF_GHP : OFF_GIP) + blockIdx.y * (64 * 1536);
    gemm_bt_tile<2, false>(A, Hc, B, Hc, C, 1536, nullptr, false,
                           blockIdx.x * 64, blockIdx.y * 64, As, Bs);
}

// ---- GRU gates + qb1 + zero RESULT: grid 64, block 512 ----
__global__ void __launch_bounds__(512) k_gate(const float* __restrict__ lh, const float* __restrict__ bih,
                                              const float* __restrict__ bhh, const float* __restrict__ b1) {
    int b = blockIdx.x, j = threadIdx.x;
    float gir = bih[j],        ghr = bhh[j];
    float giz = bih[512 + j],  ghz = bhh[512 + j];
    float gin = bih[1024 + j], ghn = bhh[1024 + j];
#pragma unroll
    for (int p = 0; p < KS; p++) {
        const float* gi = g_scr + OFF_GIP + p * (64 * 1536) + b * 1536;
        const float* gh = g_scr + OFF_GHP + p * (64 * 1536) + b * 1536;
        gir += gi[j];        ghr += gh[j];
        giz += gi[512 + j];  ghz += gh[512 + j];
        gin += gi[1024 + j]; ghn += gh[1024 + j];
    }
    float r = 1.f / (1.f + expf(-(gir + ghr)));
    float z = 1.f / (1.f + expf(-(giz + ghz)));
    float n = tanhf(gin + r * ghn);
    float hv = lh[b * Hc + j];
    float hn = (1.f - z) * n + z * hv;
    g_scr[OFF_HNEW + b * Hc + j] = hn;
    g_scr[OFF_RESULT + b * Hc + j] = 0.f;   // zero accumulator for result adds

    float p = hn * b1[j];
    __shared__ float red[16];
#pragma unroll
    for (int o = 16; o; o >>= 1) p += __shfl_xor_sync(0xffffffffu, p, o);
    if ((j & 31) == 0) red[j >> 5] = p;
    __syncthreads();
    if (j < 16) {
        float v = red[j];
#pragma unroll
        for (int o = 8; o; o >>= 1) v += __shfl_xor_sync(0x0000ffffu, v, o);
        if (j == 0) g_scr[OFF_QB1 + b] = v;
    }
}

// ---- q partials: grid (8, KS), block 256 ----
__global__ void __launch_bounds__(256) k_q(const float* __restrict__ w1) {
    __shared__ float As[32][65];
    __shared__ float Bs[32][65];
    gemm_ab_tile<2>(g_scr + OFF_HNEW, Hc, w1, Hc,
                    g_scr + OFF_QP + blockIdx.y * (64 * 512), Hc,
                    blockIdx.x * 64, blockIdx.y * 64, As, Bs);
}

// ================= MEGA: [0,64) W32=w3a@w2 (+bvec), [64,96) RESULT+=hnew@w3b^T, [96,1120) attn ====
__device__ __forceinline__ void cp_prefetch(float4* dst, const float4* src, int t) {
#pragma unroll
    for (int i = 0; i < 4; i++) {
        unsigned d = (unsigned)__cvta_generic_to_shared(dst + t + i * 256);
        asm volatile("cp.async.cg.shared.global [%0], [%1], 16;\n" :: "r"(d), "l"(src + t + i * 256));
    }
    asm volatile("cp.async.commit_group;\n");
}

__global__ void __launch_bounds__(256, 5) k_mega(const float* __restrict__ enc,
                                                 const float* __restrict__ mask,
                                                 const float* __restrict__ w2,
                                                 const float* __restrict__ b2,
                                                 const float* __restrict__ w3,
                                                 const float* __restrict__ b3) {
    __shared__ __align__(16) float sp[8784];   // 35136 B union pool
    const int t = threadIdx.x;
    const int bid = blockIdx.x;

    if (bid < 64) {
        // W32[j,k] = sum_k2 w3[j,k2]*w2[k2,k]  (j rows of w3, k2 < 512)
        float (*As)[65] = reinterpret_cast<float (*)[65]>(sp);
        float (*Bs)[65] = reinterpret_cast<float (*)[65]>(sp + 32 * 65);
        int tr = bid >> 3, tc = bid & 7;
        gemm_ab_tile<16>(w3 + tr * 64 * 1024, 1024, w2, Hc,
                         g_scr + OFF_W32 + tr * 64 * 512, Hc,
                         tc * 64, 0, As, Bs);
        if (tc == 0 && t < 64) {
            int j = tr * 64 + t;
            float s = b3[j];
            for (int k = 0; k < 512; k++) s += w3[j * 1024 + k] * b2[k];
            g_scr[OFF_BVEC + j] = s;
        }
        return;
    }
    if (bid < 96) {
        // RESULT += hnew @ w3[:,512:]^T  (bias handled via BVEC later)
        float (*As)[65] = reinterpret_cast<float (*)[65]>(sp);
        float (*Bs)[65] = reinterpret_cast<float (*)[65]>(sp + 32 * 65);
        int b2i = bid - 64;
        int jt = b2i >> 2, kt = b2i & 3;
        gemm_bt_tile<4, true>(g_scr + OFF_HNEW, Hc, w3 + 512, 1024,
                              g_scr + OFF_RESULT, Hc, nullptr, false,
                              jt * 64, kt * 128, As, Bs);
        return;
    }

    // ---------------- attention slice ----------------
    constexpr float inv_div = 0.04419417382415922f;  // 1/sqrt(512)
    float*  qs    = sp;                  // 512
    float4* buf   = reinterpret_cast<float4*>(sp + 512);  // 2*1024 float4
    float*  scs   = sp + 512 + 8192;     // 8
    float*  ws    = scs + 8;             // 8
    float*  smask = ws + 8;              // 64

    const int id = bid - 96;
    const int b = id >> 4;
    const int slice = id & 15;
    const int sbase = slice * 64;
    const float* encb = enc + (size_t)b * Sc * Hc;

    float q0 = 0.f, q1 = 0.f;
#pragma unroll
    for (int p = 0; p < KS; p++) {
        q0 += g_scr[OFF_QP + p * (64 * 512) + b * Hc + t];
        q1 += g_scr[OFF_QP + p * (64 * 512) + b * Hc + t + 256];
    }
    qs[t] = q0 * inv_div;
    qs[t + 256] = q1 * inv_div;
    if (t < 64) smask[t] = mask[b * Sc + sbase + t];
    const float cb = g_scr[OFF_QB1 + b] * inv_div;

    const int w = t >> 5, lane = t & 31;
    float m = -INFINITY, l = 0.f, a0 = 0.f, a1 = 0.f;

    cp_prefetch(buf, reinterpret_cast<const float4*>(encb + (size_t)sbase * Hc), t);

    for (int c = 0; c < 8; c++) {
        asm volatile("cp.async.wait_group 0;\n");
        __syncthreads();   // chunk c ready AND all threads done with buf[(c+1)&1]

        if (c < 7)
            cp_prefetch(buf + ((c + 1) & 1) * 1024,
                        reinterpret_cast<const float4*>(encb + (size_t)(sbase + (c + 1) * 8) * Hc), t);

        const float* ch = reinterpret_cast<const float*>(buf + (c & 1) * 1024);
        const int s0 = sbase + c * 8;

        // scores: warp w handles row w
        {
            float d = 0.f;
#pragma unroll
            for (int kk = 0; kk < 16; kk++) {
                int k = lane + kk * 32;
                d += ch[w * 512 + k] * qs[k];
            }
#pragma unroll
            for (int o = 16; o; o >>= 1) d += __shfl_xor_sync(0xffffffffu, d, o);
            if (lane == 0) {
                float sc = d + cb + smask[c * 8 + w];
                scs[w] = sc;
                g_scr[OFF_ATTN + b * Sc + s0 + w] = sc;
            }
        }
        __syncthreads();

        float cm = scs[0];
#pragma unroll
        for (int r = 1; r < 8; r++) cm = fmaxf(cm, scs[r]);
        float nm = fmaxf(m, cm);
        if (nm > m) {
            float scale = expf(m - nm);
            a0 *= scale; a1 *= scale; l *= scale;
        }
        if (t < 8) ws[t] = expf(scs[t] - nm);
        __syncthreads();

        float lsum = 0.f;
#pragma unroll
        for (int r = 0; r < 8; r++) {
            float wr = ws[r];
            lsum += wr;
            a0 += wr * ch[r * 512 + t];
            a1 += wr * ch[r * 512 + t + 256];
        }
        l += lsum;
        m = nm;
    }
    if (t == 0) { g_scr[OFF_PARTM + id] = m; g_scr[OFF_PARTL + id] = l; }
    g_scr[OFF_PARTACC + id * 512 + t]       = a0;
    g_scr[OFF_PARTACC + id * 512 + t + 256] = a1;
}

// ---- combine partials -> ctxraw, top-4, TKLOG: grid 64, block 256 ----
__global__ void __launch_bounds__(256) k_combine(const float* __restrict__ evid) {
    __shared__ float sv[1024];
    __shared__ int pick[4];
    __shared__ float pickv[4];
    __shared__ float wvv[8];
    __shared__ int wii[8];
    const int b = blockIdx.x, t = threadIdx.x;

    float pm[SLICES], e[SLICES];
    float M = -INFINITY;
#pragma unroll
    for (int p = 0; p < SLICES; p++) { pm[p] = g_scr[OFF_PARTM + b * SLICES + p]; M = fmaxf(M, pm[p]); }
    float L = 0.f;
#pragma unroll
    for (int p = 0; p < SLICES; p++) { e[p] = expf(pm[p] - M); L += g_scr[OFF_PARTL + b * SLICES + p] * e[p]; }
    float invL = 1.f / L;
#pragma unroll
    for (int half = 0; half < 2; half++) {
        int col = t + half * 256;
        float s = 0.f;
#pragma unroll
        for (int p = 0; p < SLICES; p++)
            s += e[p] * g_scr[OFF_PARTACC + (b * SLICES + p) * 512 + col];
        g_scr[OFF_CTXRAW + b * Hc + col] = s * invL;
    }
#pragma unroll
    for (int i = 0; i < 4; i++) sv[t + i * 256] = g_scr[OFF_ATTN + b * Sc + t + i * 256];
    __syncthreads();
    for (int round = 0; round < 4; round++) {
        float best = -INFINITY;
        int bi = 0x7fffffff;
#pragma unroll
        for (int u = 0; u < 4; u++) {
            int idx = t * 4 + u;
            bool skip = false;
            for (int rr = 0; rr < round; rr++) skip |= (pick[rr] == idx);
            float v = sv[idx];
            if (!skip && (v > best || (v == best && idx < bi))) { best = v; bi = idx; }
        }
#pragma unroll
        for (int o = 16; o; o >>= 1) {
            float ov = __shfl_xor_sync(0xffffffffu, best, o);
            int   oi = __shfl_xor_sync(0xffffffffu, bi, o);
            if (ov > best || (ov == best && oi < bi)) { best = ov; bi = oi; }
        }
        if ((t & 31) == 0) { wvv[t >> 5] = best; wii[t >> 5] = bi; }
        __syncthreads();
        if (t == 0) {
            float bb = wvv[0]; int bj = wii[0];
            for (int k = 1; k < 8; k++)
                if (wvv[k] > bb || (wvv[k] == bb && wii[k] < bj)) { bb = wvv[k]; bj = wii[k]; }
            pick[round] = bj; pickv[round] = bb;
        }
        __syncthreads();
    }
    if (t < 4) {
        g_scr[OFF_TKLOG + b * 4 + t] = (M - pickv[t]) + logf(L) + evid[b];
        g_tkidx[b * 4 + t] = pick[t];
    }
}

// ---- res2: RESULT += ctxraw @ W32^T + bvec : grid (8, KS) ----
__global__ void __launch_bounds__(256) k_res2() {
    __shared__ float As[32][65];
    __shared__ float Bs[32][65];
    gemm_bt_tile<2, true>(g_scr + OFF_CTXRAW, Hc, g_scr + OFF_W32, Hc,
                          g_scr + OFF_RESULT, Hc, g_scr + OFF_BVEC, blockIdx.y == 0,
                          blockIdx.x * 64, blockIdx.y * 64, As, Bs);
}

// ---- gather (with fused beam selection): grid 768, block 512 ----
__global__ void __launch_bounds__(512) k_gather(const int* __restrict__ esi,
                                                const float* __restrict__ prev_scores,
                                                const float* __restrict__ mask,
                                                float* __restrict__ out) {
    __shared__ int ssels[64];
    __shared__ int ssent[64];
    const int t = threadIdx.x;
    const int wb = t >> 5, lane = t & 31;   // 16 warps = 16 batches

    {
        float v = (lane < 16) ? g_scr[OFF_TKLOG + wb * 16 + lane] : INFINITY;
        int rank = 0;
#pragma unroll
        for (int j = 0; j < 16; j++) {
            float vj = __shfl_sync(0xffffffffu, v, j);
            rank += (vj < v) || (vj == v && j < lane);
        }
        if (lane < 16 && rank < 4) {
            int k = wb * 4 + rank;
            int s = wb * 4 + (lane >> 2);
            int rr = lane & 3;
            int sent = g_tkidx[s * 4 + rr];
            ssels[k] = s;
            ssent[k] = sent;
            if (blockIdx.x == 0) {
                out[O_SCORES + k] = v;
                out[O_IDX + k * 4 + 0] = (float)esi[s * 3 + 0];
                out[O_IDX + k * 4 + 1] = (float)esi[s * 3 + 1];
                out[O_IDX + k * 4 + 2] = (float)esi[s * 3 + 2];
                out[O_IDX + k * 4 + 3] = (float)sent;
            }
        }
    }
    __syncthreads();

    int i = blockIdx.x * 512 + t;   // 768*512 = 393216 exact
    if (i < 32768) {
        int bi = i >> 9, j = i & 511;
        out[O_RESULT + i] = g_scr[OFF_RESULT + ssels[bi] * 512 + j];
    } else if (i < 65536) {
        int j = i - 32768;
        out[O_HIDDEN + j] = g_scr[OFF_HNEW + ssels[j >> 9] * 512 + (j & 511)];
    } else if (i < 327680) {
        int j = i - 65536;
        int p = j >> 16;
        int rem = j & 65535;
        int bi = rem >> 10, scol = rem & 1023;
        int s = ssels[bi];
        float v = (p < 3) ? prev_scores[p * 65536 + s * 1024 + scol]
                          : g_scr[OFF_ATTN + s * 1024 + scol];
        out[O_ATTNS + j] = v;
    } else {
        int j = i - 327680;
        int bi = j >> 10, scol = j & 1023;
        int s = ssels[bi];
        float v = (scol == ssent[bi]) ? NEG_INF_VAL : mask[s * 1024 + scol];
        out[O_MASK + j] = v;
    }
}

// ---------------- launch ----------------
extern "C" void kernel_launch(void* const* d_in, const int* in_sizes, int n_in,
                              void* d_out, int out_size) {
    const float* last_hidden = (const float*)d_in[0];
    const float* dec_inputs  = (const float*)d_in[1];
    const float* enc         = (const float*)d_in[2];
    const float* prev_scores = (const float*)d_in[3];
    const float* mask        = (const float*)d_in[4];
    const float* evid        = (const float*)d_in[5];
    const int*   esi         = (const int*)d_in[6];
    const float* w1  = (const float*)d_in[7];
    const float* b1  = (const float*)d_in[8];
    const float* w2  = (const float*)d_in[9];
    const float* b2  = (const float*)d_in[10];
    const float* w3  = (const float*)d_in[11];
    const float* b3  = (const float*)d_in[12];
    const float* wih = (const float*)d_in[13];
    const float* whh = (const float*)d_in[14];
    const float* bih = (const float*)d_in[15];
    const float* bhh = (const float*)d_in[16];
    float* out = (float*)d_out;

    k_gru<<<dim3(24, KS, 2), 256>>>(dec_inputs, last_hidden, wih, whh);
    k_gate<<<64, 512>>>(last_hidden, bih, bhh, b1);
    k_q<<<dim3(8, KS), 256>>>(w1);
    k_mega<<<1120, 256>>>(enc, mask, w2, b2, w3, b3);
    k_combine<<<64, 256>>>(evid);
    k_res2<<<dim3(8, KS), 256>>>();
    k_gather<<<768, 512>>>(esi, prev_scores, mask, out);
}

// round 7
// speedup vs baseline: 2.1901x; 2.1901x over previous
#include <cuda_runtime.h>
#include <math.h>

#define NEG_INF_VAL -10000000000.0f

namespace {
constexpr int Hc = 512;
constexpr int Sc = 1024;
constexpr int KS = 8;          // split-K for H=512 GEMMs
constexpr int SLICES = 16;     // attn slices per beam
constexpr int NPART = 64 * SLICES;  // 1024

// float scratch offsets
constexpr int OFF_GIP     = 0;                          // KS*64*1536
constexpr int OFF_GHP     = OFF_GIP + KS * 64 * 1536;
constexpr int OFF_QP      = OFF_GHP + KS * 64 * 1536;   // 64*512 (atomic-accumulated)
constexpr int OFF_HNEW    = OFF_QP + 64 * 512;
constexpr int OFF_QB1     = OFF_HNEW + 64 * 512;
constexpr int OFF_ATTN    = OFF_QB1 + 64;               // 64x1024
constexpr int OFF_PARTM   = OFF_ATTN + 64 * 1024;
constexpr int OFF_PARTL   = OFF_PARTM + NPART;
constexpr int OFF_PARTACC = OFF_PARTL + NPART;          // 1024*512
constexpr int OFF_CTXRAW  = OFF_PARTACC + NPART * 512;
constexpr int OFF_CTX     = OFF_CTXRAW + 64 * 512;
constexpr int OFF_RESULT  = OFF_CTX + 64 * 512;
constexpr int OFF_TKLOG   = OFF_RESULT + 64 * 512;
constexpr int SCR_TOTAL   = OFF_TKLOG + 256;

// output layout (floats), tuple members concatenated in order
constexpr int O_RESULT = 0;
constexpr int O_HIDDEN = 32768;
constexpr int O_IDX    = 65536;
constexpr int O_ATTNS  = 65792;
constexpr int O_MASK   = 327936;
constexpr int O_SCORES = 393472;
}

__device__ __align__(16) float g_scr[SCR_TOTAL];
__device__ int g_tkidx[256];

// ---------------- GEMM tiles (64 rows x 64 cols, K-chunk = ITERS*32) ----------------
template<int ITERS, bool ATOMIC>
__device__ __forceinline__ void gemm_bt_tile(const float* __restrict__ A, int lda,
                                             const float* __restrict__ B, int ldb,
                                             float* __restrict__ C, int ldc,
                                             const float* __restrict__ bias, bool addBias,
                                             int j0, int k0,
                                             float (*As)[65], float (*Bs)[65]) {
    const int t = threadIdx.x;
    const int bx = (t & 15) * 4;
    const int by = (t >> 4) * 4;
    float acc[4][4] = {};
#pragma unroll
    for (int it = 0; it < ITERS; it++) {
        const int kk = k0 + it * 32;
#pragma unroll
        for (int i = 0; i < 8; i++) {
            int idx = t + i * 256;
            int r = idx >> 5, c = idx & 31;
            As[c][r] = A[r * lda + kk + c];
            Bs[c][r] = B[(j0 + r) * ldb + kk + c];
        }
        __syncthreads();
#pragma unroll
        for (int c = 0; c < 32; c++) {
            float b0 = Bs[c][bx + 0], b1 = Bs[c][bx + 1], b2 = Bs[c][bx + 2], b3 = Bs[c][bx + 3];
#pragma unroll
            for (int r = 0; r < 4; r++) {
                float av = As[c][by + r];
                acc[r][0] += av * b0; acc[r][1] += av * b1;
                acc[r][2] += av * b2; acc[r][3] += av * b3;
            }
        }
        __syncthreads();
    }
#pragma unroll
    for (int r = 0; r < 4; r++)
#pragma unroll
        for (int cc = 0; cc < 4; cc++) {
            float v = acc[r][cc];
            if (addBias) v += bias[j0 + bx + cc];
            if (ATOMIC) atomicAdd(&C[(by + r) * ldc + j0 + bx + cc], v);
            else        C[(by + r) * ldc + j0 + bx + cc] = v;
        }
}

template<int ITERS, bool ATOMIC>
__device__ __forceinline__ void gemm_ab_tile(const float* __restrict__ A, int lda,
                                             const float* __restrict__ B, int ldb,
                                             float* __restrict__ C, int ldc,
                                             int j0, int k0,
                                             float (*As)[65], float (*Bs)[65]) {
    const int t = threadIdx.x;
    const int bx = (t & 15) * 4;
    const int by = (t >> 4) * 4;
    float acc[4][4] = {};
#pragma unroll
    for (int it = 0; it < ITERS; it++) {
        const int kk = k0 + it * 32;
#pragma unroll
        for (int i = 0; i < 8; i++) {
            int idx = t + i * 256;
            int r = idx >> 5, c = idx & 31;
            As[c][r] = A[r * lda + kk + c];
        }
#pragma unroll
        for (int i = 0; i < 8; i++) {
            int idx = t + i * 256;
            int c = idx >> 6, jj = idx & 63;
            Bs[c][jj] = B[(kk + c) * ldb + j0 + jj];
        }
        __syncthreads();
#pragma unroll
        for (int c = 0; c < 32; c++) {
            float b0 = Bs[c][bx + 0], b1 = Bs[c][bx + 1], b2 = Bs[c][bx + 2], b3 = Bs[c][bx + 3];
#pragma unroll
            for (int r = 0; r < 4; r++) {
                float av = As[c][by + r];
                acc[r][0] += av * b0; acc[r][1] += av * b1;
                acc[r][2] += av * b2; acc[r][3] += av * b3;
            }
        }
        __syncthreads();
    }
#pragma unroll
    for (int r = 0; r < 4; r++)
#pragma unroll
        for (int cc = 0; cc < 4; cc++) {
            if (ATOMIC) atomicAdd(&C[(by + r) * ldc + j0 + bx + cc], acc[r][cc]);
            else        C[(by + r) * ldc + j0 + bx + cc] = acc[r][cc];
        }
}

// ---- gi/gh partials: grid (24, KS, 2), block 256 ----
__global__ void __launch_bounds__(256) k_gru(const float* __restrict__ x, const float* __restrict__ h,
                                             const float* __restrict__ wih, const float* __restrict__ whh) {
    __shared__ float As[32][65];
    __shared__ float Bs[32][65];
    const float* A = blockIdx.z ? h : x;
    const float* B = blockIdx.z ? whh : wih;
    float* C = g_scr + (blockIdx.z ? OFF_GHP : OFF_GIP) + blockIdx.y * (64 * 1536);
    gemm_bt_tile<2, false>(A, Hc, B, Hc, C, 1536, nullptr, false,
                           blockIdx.x * 64, blockIdx.y * 64, As, Bs);
}

// ---- GRU gates + qb1 + zero RESULT/QP: grid 64, block 512 ----
__global__ void __launch_bounds__(512) k_gate(const float* __restrict__ lh, const float* __restrict__ bih,
                                              const float* __restrict__ bhh, const float* __restrict__ b1) {
    int b = blockIdx.x, j = threadIdx.x;
    float gir = bih[j],        ghr = bhh[j];
    float giz = bih[512 + j],  ghz = bhh[512 + j];
    float gin = bih[1024 + j], ghn = bhh[1024 + j];
#pragma unroll
    for (int p = 0; p < KS; p++) {
        const float* gi = g_scr + OFF_GIP + p * (64 * 1536) + b * 1536;
        const float* gh = g_scr + OFF_GHP + p * (64 * 1536) + b * 1536;
        gir += gi[j];        ghr += gh[j];
        giz += gi[512 + j];  ghz += gh[512 + j];
        gin += gi[1024 + j]; ghn += gh[1024 + j];
    }
    float r = 1.f / (1.f + expf(-(gir + ghr)));
    float z = 1.f / (1.f + expf(-(giz + ghz)));
    float n = tanhf(gin + r * ghn);
    float hv = lh[b * Hc + j];
    float hn = (1.f - z) * n + z * hv;
    g_scr[OFF_HNEW + b * Hc + j] = hn;
    g_scr[OFF_RESULT + b * Hc + j] = 0.f;   // zero accumulator for result adds
    g_scr[OFF_QP + b * Hc + j] = 0.f;       // zero accumulator for q atomics

    float p = hn * b1[j];
    __shared__ float red[16];
#pragma unroll
    for (int o = 16; o; o >>= 1) p += __shfl_xor_sync(0xffffffffu, p, o);
    if ((j & 31) == 0) red[j >> 5] = p;
    __syncthreads();
    if (j < 16) {
        float v = red[j];
#pragma unroll
        for (int o = 8; o; o >>= 1) v += __shfl_xor_sync(0x0000ffffu, v, o);
        if (j == 0) g_scr[OFF_QB1 + b] = v;
    }
}

// ---- q (z=0, atomic into QP) + RESULT += hnew @ w3[:,512:]^T + b3 (z=1): grid (8, KS, 2) ----
__global__ void __launch_bounds__(256) k_q2(const float* __restrict__ w1,
                                            const float* __restrict__ w3,
                                            const float* __restrict__ b3) {
    __shared__ float As[32][65];
    __shared__ float Bs[32][65];
    if (blockIdx.z == 0) {
        gemm_ab_tile<2, true>(g_scr + OFF_HNEW, Hc, w1, Hc,
                              g_scr + OFF_QP, Hc,
                              blockIdx.x * 64, blockIdx.y * 64, As, Bs);
    } else {
        gemm_bt_tile<2, true>(g_scr + OFF_HNEW, Hc, w3 + 512, 1024,
                              g_scr + OFF_RESULT, Hc, b3, blockIdx.y == 0,
                              blockIdx.x * 64, blockIdx.y * 64, As, Bs);
    }
}

// ================= ATTN: streaming score + online softmax + context ===========
// grid 1024 (16 slices/beam), block 256, 64 rows/block in 16 chunks of 4 rows.
// smem ~18.6KB, regs capped for 8 blocks/SM -> all 1024 blocks in ONE wave.
__device__ __forceinline__ void cp_prefetch4(float4* dst, const float4* src, int t) {
#pragma unroll
    for (int i = 0; i < 2; i++) {
        unsigned d = (unsigned)__cvta_generic_to_shared(dst + t + i * 256);
        asm volatile("cp.async.cg.shared.global [%0], [%1], 16;\n" :: "r"(d), "l"(src + t + i * 256));
    }
    asm volatile("cp.async.commit_group;\n");
}

__global__ void __launch_bounds__(256, 8) k_attn(const float* __restrict__ enc,
                                                 const float* __restrict__ mask) {
    constexpr float inv_div = 0.04419417382415922f;  // 1/sqrt(512)
    __shared__ float qs[512];
    __shared__ float4 buf[2][512];   // 2 x (4 rows x 512 f32) = 16KB
    __shared__ float scs[4];
    __shared__ float ws[4];
    __shared__ float smask[64];

    const int t = threadIdx.x;
    const int b = blockIdx.x >> 4;
    const int slice = blockIdx.x & 15;
    const int sbase = slice * 64;
    const float* encb = enc + (size_t)b * Sc * Hc;

    qs[t]       = g_scr[OFF_QP + b * Hc + t] * inv_div;
    qs[t + 256] = g_scr[OFF_QP + b * Hc + t + 256] * inv_div;
    if (t < 64) smask[t] = mask[b * Sc + sbase + t];
    const float cb = g_scr[OFF_QB1 + b] * inv_div;

    const int w = t >> 5, lane = t & 31;
    float m = -INFINITY, l = 0.f, a0 = 0.f, a1 = 0.f;

    cp_prefetch4(buf[0], reinterpret_cast<const float4*>(encb + (size_t)sbase * Hc), t);

    for (int c = 0; c < 16; c++) {
        asm volatile("cp.async.wait_group 0;\n");
        __syncthreads();   // chunk c ready AND all threads done with buf[(c+1)&1]

        if (c < 15)
            cp_prefetch4(buf[(c + 1) & 1],
                         reinterpret_cast<const float4*>(encb + (size_t)(sbase + (c + 1) * 4) * Hc), t);

        const float* ch = reinterpret_cast<const float*>(buf[c & 1]);
        const int s0 = sbase + c * 4;

        // scores: warps 0-3 each compute one row
        if (w < 4) {
            float d = 0.f;
#pragma unroll
            for (int kk = 0; kk < 16; kk++) {
                int k = lane + kk * 32;
                d += ch[w * 512 + k] * qs[k];
            }
#pragma unroll
            for (int o = 16; o; o >>= 1) d += __shfl_xor_sync(0xffffffffu, d, o);
            if (lane == 0) {
                float sc = d + cb + smask[c * 4 + w];
                scs[w] = sc;
                g_scr[OFF_ATTN + b * Sc + s0 + w] = sc;
            }
        }
        __syncthreads();

        float cm = fmaxf(fmaxf(scs[0], scs[1]), fmaxf(scs[2], scs[3]));
        float nm = fmaxf(m, cm);
        if (nm > m) {
            float scale = expf(m - nm);
            a0 *= scale; a1 *= scale; l *= scale;
        }
        if (t < 4) ws[t] = expf(scs[t] - nm);
        __syncthreads();

        float lsum = 0.f;
#pragma unroll
        for (int r = 0; r < 4; r++) {
            float wr = ws[r];
            lsum += wr;
            a0 += wr * ch[r * 512 + t];
            a1 += wr * ch[r * 512 + t + 256];
        }
        l += lsum;
        m = nm;
        // next iteration's first sync protects ch/ws/scs
    }
    const int pid = blockIdx.x;
    if (t == 0) { g_scr[OFF_PARTM + pid] = m; g_scr[OFF_PARTL + pid] = l; }
    g_scr[OFF_PARTACC + pid * 512 + t]       = a0;
    g_scr[OFF_PARTACC + pid * 512 + t + 256] = a1;
}

// ---- combine partials -> ctxraw, zero CTX, top-4, TKLOG: grid 64, block 256 ----
__global__ void __launch_bounds__(256) k_combine(const float* __restrict__ evid) {
    __shared__ float sv[1024];
    __shared__ int pick[4];
    __shared__ float pickv[4];
    __shared__ float wvv[8];
    __shared__ int wii[8];
    const int b = blockIdx.x, t = threadIdx.x;

    float pm[SLICES], e[SLICES];
    float M = -INFINITY;
#pragma unroll
    for (int p = 0; p < SLICES; p++) { pm[p] = g_scr[OFF_PARTM + b * SLICES + p]; M = fmaxf(M, pm[p]); }
    float L = 0.f;
#pragma unroll
    for (int p = 0; p < SLICES; p++) { e[p] = expf(pm[p] - M); L += g_scr[OFF_PARTL + b * SLICES + p] * e[p]; }
    float invL = 1.f / L;
#pragma unroll
    for (int half = 0; half < 2; half++) {
        int col = t + half * 256;
        float s = 0.f;
#pragma unroll
        for (int p = 0; p < SLICES; p++)
            s += e[p] * g_scr[OFF_PARTACC + (b * SLICES + p) * 512 + col];
        g_scr[OFF_CTXRAW + b * Hc + col] = s * invL;
        g_scr[OFF_CTX + b * Hc + col] = 0.f;
    }
#pragma unroll
    for (int i = 0; i < 4; i++) sv[t + i * 256] = g_scr[OFF_ATTN + b * Sc + t + i * 256];
    __syncthreads();
    for (int round = 0; round < 4; round++) {
        float best = -INFINITY;
        int bi = 0x7fffffff;
#pragma unroll
        for (int u = 0; u < 4; u++) {
            int idx = t * 4 + u;
            bool skip = false;
            for (int rr = 0; rr < round; rr++) skip |= (pick[rr] == idx);
            float v = sv[idx];
            if (!skip && (v > best || (v == best && idx < bi))) { best = v; bi = idx; }
        }
#pragma unroll
        for (int o = 16; o; o >>= 1) {
            float ov = __shfl_xor_sync(0xffffffffu, best, o);
            int   oi = __shfl_xor_sync(0xffffffffu, bi, o);
            if (ov > best || (ov == best && oi < bi)) { best = ov; bi = oi; }
        }
        if ((t & 31) == 0) { wvv[t >> 5] = best; wii[t >> 5] = bi; }
        __syncthreads();
        if (t == 0) {
            float bb = wvv[0]; int bj = wii[0];
            for (int k = 1; k < 8; k++)
                if (wvv[k] > bb || (wvv[k] == bb && wii[k] < bj)) { bb = wvv[k]; bj = wii[k]; }
            pick[round] = bj; pickv[round] = bb;
        }
        __syncthreads();
    }
    if (t < 4) {
        g_scr[OFF_TKLOG + b * 4 + t] = (M - pickv[t]) + logf(L) + evid[b];
        g_tkidx[b * 4 + t] = pick[t];
    }
}

// ---- ctx GEMM: CTX += ctxraw @ w2^T + b2 : grid (8, KS) ----
__global__ void __launch_bounds__(256) k_ctx(const float* __restrict__ w2, const float* __restrict__ b2) {
    __shared__ float As[32][65];
    __shared__ float Bs[32][65];
    gemm_bt_tile<2, true>(g_scr + OFF_CTXRAW, Hc, w2, Hc,
                          g_scr + OFF_CTX, Hc, b2, blockIdx.y == 0,
                          blockIdx.x * 64, blockIdx.y * 64, As, Bs);
}

// ---- res GEMM: RESULT += CTX @ w3[:, :512]^T : grid (8, KS) ----
__global__ void __launch_bounds__(256) k_res(const float* __restrict__ w3) {
    __shared__ float As[32][65];
    __shared__ float Bs[32][65];
    gemm_bt_tile<2, true>(g_scr + OFF_CTX, Hc, w3, 1024,
                          g_scr + OFF_RESULT, Hc, nullptr, false,
                          blockIdx.x * 64, blockIdx.y * 64, As, Bs);
}

// ---- gather (with fused beam selection): grid 768, block 512 ----
__global__ void __launch_bounds__(512) k_gather(const int* __restrict__ esi,
                                                const float* __restrict__ prev_scores,
                                                const float* __restrict__ mask,
                                                float* __restrict__ out) {
    __shared__ int ssels[64];
    __shared__ int ssent[64];
    const int t = threadIdx.x;
    const int wb = t >> 5, lane = t & 31;   // 16 warps = 16 batches

    {
        float v = (lane < 16) ? g_scr[OFF_TKLOG + wb * 16 + lane] : INFINITY;
        int rank = 0;
#pragma unroll
        for (int j = 0; j < 16; j++) {
            float vj = __shfl_sync(0xffffffffu, v, j);
            rank += (vj < v) || (vj == v && j < lane);
        }
        if (lane < 16 && rank < 4) {
            int k = wb * 4 + rank;
            int s = wb * 4 + (lane >> 2);
            int rr = lane & 3;
            int sent = g_tkidx[s * 4 + rr];
            ssels[k] = s;
            ssent[k] = sent;
            if (blockIdx.x == 0) {
                out[O_SCORES + k] = v;
                out[O_IDX + k * 4 + 0] = (float)esi[s * 3 + 0];
                out[O_IDX + k * 4 + 1] = (float)esi[s * 3 + 1];
                out[O_IDX + k * 4 + 2] = (float)esi[s * 3 + 2];
                out[O_IDX + k * 4 + 3] = (float)sent;
            }
        }
    }
    __syncthreads();

    int i = blockIdx.x * 512 + t;   // 768*512 = 393216 exact
    if (i < 32768) {
        int bi = i >> 9, j = i & 511;
        out[O_RESULT + i] = g_scr[OFF_RESULT + ssels[bi] * 512 + j];
    } else if (i < 65536) {
        int j = i - 32768;
        out[O_HIDDEN + j] = g_scr[OFF_HNEW + ssels[j >> 9] * 512 + (j & 511)];
    } else if (i < 327680) {
        int j = i - 65536;
        int p = j >> 16;
        int rem = j & 65535;
        int bi = rem >> 10, scol = rem & 1023;
        int s = ssels[bi];
        float v = (p < 3) ? prev_scores[p * 65536 + s * 1024 + scol]
                          : g_scr[OFF_ATTN + s * 1024 + scol];
        out[O_ATTNS + j] = v;
    } else {
        int j = i - 327680;
        int bi = j >> 10, scol = j & 1023;
        int s = ssels[bi];
        float v = (scol == ssent[bi]) ? NEG_INF_VAL : mask[s * 1024 + scol];
        out[O_MASK + j] = v;
    }
}

// ---------------- launch ----------------
extern "C" void kernel_launch(void* const* d_in, const int* in_sizes, int n_in,
                              void* d_out, int out_size) {
    const float* last_hidden = (const float*)d_in[0];
    const float* dec_inputs  = (const float*)d_in[1];
    const float* enc         = (const float*)d_in[2];
    const float* prev_scores = (const float*)d_in[3];
    const float* mask        = (const float*)d_in[4];
    const float* evid        = (const float*)d_in[5];
    const int*   esi         = (const int*)d_in[6];
    const float* w1  = (const float*)d_in[7];
    const float* b1  = (const float*)d_in[8];
    const float* w2  = (const float*)d_in[9];
    const float* b2  = (const float*)d_in[10];
    const float* w3  = (const float*)d_in[11];
    const float* b3  = (const float*)d_in[12];
    const float* wih = (const float*)d_in[13];
    const float* whh = (const float*)d_in[14];
    const float* bih = (const float*)d_in[15];
    const float* bhh = (const float*)d_in[16];
    float* out = (float*)d_out;

    k_gru<<<dim3(24, KS, 2), 256>>>(dec_inputs, last_hidden, wih, whh);
    k_gate<<<64, 512>>>(last_hidden, bih, bhh, b1);
    k_q2<<<dim3(8, KS, 2), 256>>>(w1, w3, b3);
    k_attn<<<1024, 256>>>(enc, mask);
    k_combine<<<64, 256>>>(evid);
    k_ctx<<<dim3(8, KS), 256>>>(w2, b2);
    k_res<<<dim3(8, KS), 256>>>(w3);
    k_gather<<<768, 512>>>(esi, prev_scores, mask, out);
}